// round 2
// baseline (speedup 1.0000x reference)
#include <cuda_runtime.h>
#include <cstdint>

// Problem dims (fixed by the dataset)
#define MDIM 8192
#define KDIM 4096
#define NDIM 4096

// ---------------- device scratch (sanctioned: __device__ globals) ----------
__device__ float g_weff[(size_t)NDIM * KDIM];   // 64 MB: dequant + lora folded, tf32-rounded
__device__ float g_x[(size_t)MDIM * KDIM];      // 128 MB: x pre-rounded to tf32 (RNA)

// ---------------- helpers ---------------------------------------------------
__device__ __forceinline__ uint32_t smem_u32(const void* p) {
    uint32_t a;
    asm("{ .reg .u64 t; cvta.to.shared.u64 t, %1; cvt.u32.u64 %0, t; }" : "=r"(a) : "l"(p));
    return a;
}
__device__ __forceinline__ float to_tf32(float f) {
    uint32_t r;
    asm("cvt.rna.tf32.f32 %0, %1;" : "=r"(r) : "f"(f));
    return __uint_as_float(r);
}
__device__ __forceinline__ void cp16(uint32_t dst, const void* src) {
    asm volatile("cp.async.cg.shared.global [%0], [%1], 16;" :: "r"(dst), "l"(src));
}
__device__ __forceinline__ void cp_commit() {
    asm volatile("cp.async.commit_group;" ::: "memory");
}
template <int N>
__device__ __forceinline__ void cp_wait() {
    asm volatile("cp.async.wait_group %0;" :: "n"(N) : "memory");
}
__device__ __forceinline__ void ldsm4(uint32_t r[4], uint32_t addr) {
    asm volatile("ldmatrix.sync.aligned.m8n8.x4.shared.b16 {%0,%1,%2,%3}, [%4];"
                 : "=r"(r[0]), "=r"(r[1]), "=r"(r[2]), "=r"(r[3]) : "r"(addr));
}
__device__ __forceinline__ void mma8(float c[4], const uint32_t a[4],
                                     uint32_t b0, uint32_t b1) {
    asm volatile("mma.sync.aligned.m16n8k8.row.col.f32.tf32.tf32.f32 "
                 "{%0,%1,%2,%3}, {%4,%5,%6,%7}, {%8,%9}, {%0,%1,%2,%3};"
                 : "+f"(c[0]), "+f"(c[1]), "+f"(c[2]), "+f"(c[3])
                 : "r"(a[0]), "r"(a[1]), "r"(a[2]), "r"(a[3]), "r"(b0), "r"(b1));
}

// ---------------- kernel 1: round x to tf32 (RNA, unbiased) ----------------
__global__ void __launch_bounds__(256) round_x_kernel(const float4* __restrict__ x,
                                                      float4* __restrict__ gx) {
    int i = blockIdx.x * 256 + threadIdx.x;
    float4 v = x[i];
    v.x = to_tf32(v.x); v.y = to_tf32(v.y); v.z = to_tf32(v.z); v.w = to_tf32(v.w);
    gx[i] = v;
}

// ---------------- kernel 2: W_eff = dequant(q,scale) + wtscale * up@down ---
__global__ void __launch_bounds__(256) prep_weight_kernel(
    const int* __restrict__ qweight, const float* __restrict__ wscales,
    const float* __restrict__ proj_down, const float* __restrict__ proj_up,
    const float* __restrict__ wtscale)
{
    __shared__ float up_s[16 * 32];
    const int n0 = blockIdx.y * 16;
    const int tid = threadIdx.x;
    #pragma unroll
    for (int j = tid; j < 512; j += 256) {
        int n = j >> 5, r = j & 31;
        up_s[j] = proj_up[(size_t)(n0 + n) * 32 + r];
    }
    __syncthreads();
    const float wt = wtscale[0];
    const int k2 = blockIdx.x * 256 + tid;   // pair index; k = 2*k2, 2*k2+1

    float ae[16], ao[16];
    #pragma unroll
    for (int n = 0; n < 16; n++) { ae[n] = 0.f; ao[n] = 0.f; }
    #pragma unroll 4
    for (int r = 0; r < 32; r++) {
        float2 d2 = *reinterpret_cast<const float2*>(proj_down + (size_t)r * KDIM + 2 * k2);
        #pragma unroll
        for (int n = 0; n < 16; n++) {
            float u = up_s[n * 32 + r];
            ae[n] = fmaf(u, d2.x, ae[n]);
            ao[n] = fmaf(u, d2.y, ao[n]);
        }
    }
    const int g = k2 >> 5;  // (2*k2)/64
    #pragma unroll
    for (int n = 0; n < 16; n++) {
        int q = qweight[(size_t)(n0 + n) * (KDIM / 2) + k2];
        float s = wscales[(size_t)g * NDIM + (n0 + n)];
        float2 w;
        w.x = to_tf32(fmaf((float)((q & 15) - 8), s, wt * ae[n]));
        w.y = to_tf32(fmaf((float)(((q >> 4) & 15) - 8), s, wt * ao[n]));
        *reinterpret_cast<float2*>(g_weff + (size_t)(n0 + n) * KDIM + 2 * k2) = w;
    }
}

// ---------------- kernel 3: tf32 mma.sync GEMM ------------------------------
// out[m0:m0+128, n0:n0+128] = g_x @ g_weff^T + bias
#define BM 128
#define BN 128
#define BK 32
#define STAGES 3
#define KTILES (KDIM / BK)            // 128
#define A_BYTES (BM * BK * 4)         // 16384
#define STAGE_BYTES (2 * A_BYTES)     // 32768 (A then B)
#define SMEM_TOTAL (STAGES * STAGE_BYTES)

__global__ void __launch_bounds__(128, 2) gemm_tf32_kernel(
    const float* __restrict__ bias, float* __restrict__ out)
{
    extern __shared__ char smem_raw[];
    const uint32_t sbase = smem_u32(smem_raw);

    const int tid  = threadIdx.x;
    const int lane = tid & 31;
    const int warp = tid >> 5;
    const int wm = warp & 1;          // 2 warps in m -> warp tile 64 rows
    const int wn = warp >> 1;         // 2 warps in n -> warp tile 64 cols
    const int m0 = blockIdx.y * BM;
    const int n0 = blockIdx.x * BN;

    // ---- cp.async source/dest (thread t owns A row t and B row t) ----
    const char* srcA = (const char*)(g_x    + (size_t)(m0 + tid) * KDIM);
    const char* srcB = (const char*)(g_weff + (size_t)(n0 + tid) * KDIM);
    const uint32_t dstRow = sbase + (uint32_t)tid * 128;  // within-stage A row base
    const int rsw = tid & 7;                               // store swizzle

    // ---- ldmatrix per-lane addressing ----
    const int lr = lane & 7;
    const int g1 = (lane >> 3) & 1;
    const int g2 = lane >> 4;
    // A x4: matrices (a0,a1,a2,a3): row += 8 on g1, chunk += 1 on g2
    const uint32_t aOff = (uint32_t)(wm * 64 + lr + (g1 << 3)) * 128;
    // B x4: (b0,b1 of nt | b0,b1 of nt+1): row += 8 on g2, chunk += 1 on g1
    const uint32_t bOff = (uint32_t)(wn * 64 + lr + (g2 << 3)) * 128;

    float acc[4][8][4];
    #pragma unroll
    for (int i = 0; i < 4; i++)
        #pragma unroll
        for (int j = 0; j < 8; j++)
            #pragma unroll
            for (int c = 0; c < 4; c++) acc[i][j][c] = 0.f;

    // ---- stage loader ----
    auto load_stage = [&](int st, int kt) {
        uint32_t sa = dstRow + (uint32_t)st * STAGE_BYTES;
        const char* ga = srcA + (size_t)kt * (BK * 4);
        const char* gb = srcB + (size_t)kt * (BK * 4);
        #pragma unroll
        for (int c = 0; c < 8; c++) {
            uint32_t off = (uint32_t)((c ^ rsw) << 4);
            cp16(sa + off,           ga + c * 16);
            cp16(sa + A_BYTES + off, gb + c * 16);
        }
    };

    // ---- prologue: prefetch 2 stages ----
    load_stage(0, 0); cp_commit();
    load_stage(1, 1); cp_commit();

    int st = 0;
    for (int kt = 0; kt < KTILES; kt++) {
        cp_wait<1>();
        __syncthreads();

        // prefetch kt+2 into the stage consumed at kt-1
        if (kt + 2 < KTILES) {
            int st2 = st + 2; if (st2 >= STAGES) st2 -= STAGES;
            load_stage(st2, kt + 2);
        }
        cp_commit();

        const uint32_t aSt = sbase + (uint32_t)st * STAGE_BYTES + aOff;
        const uint32_t bSt = sbase + (uint32_t)st * STAGE_BYTES + A_BYTES + bOff;

        #pragma unroll
        for (int s = 0; s < 4; s++) {           // 4 k-steps of 8
            uint32_t a[4][4], b[4][4];
            const uint32_t xA = (uint32_t)(((2 * s + g2) ^ lr) << 4);
            const uint32_t xB = (uint32_t)(((2 * s + g1) ^ lr) << 4);
            #pragma unroll
            for (int mt = 0; mt < 4; mt++) ldsm4(a[mt], aSt + mt * 2048 + xA);
            #pragma unroll
            for (int p = 0; p < 4; p++)    ldsm4(b[p], bSt + p * 2048 + xB);
            #pragma unroll
            for (int mt = 0; mt < 4; mt++) {
                #pragma unroll
                for (int p = 0; p < 4; p++) {
                    mma8(acc[mt][2 * p],     a[mt], b[p][0], b[p][1]);
                    mma8(acc[mt][2 * p + 1], a[mt], b[p][2], b[p][3]);
                }
            }
        }
        if (++st == STAGES) st = 0;
    }

    // ---- epilogue: add bias, store float2 ----
    const int mrow = m0 + wm * 64 + (lane >> 2);
    const int ncol = n0 + wn * 64 + 2 * (lane & 3);
    float2 bv[8];
    #pragma unroll
    for (int nt = 0; nt < 8; nt++)
        bv[nt] = *reinterpret_cast<const float2*>(bias + ncol + nt * 8);

    #pragma unroll
    for (int mt = 0; mt < 4; mt++) {
        float* r0 = out + (size_t)(mrow + mt * 16) * NDIM + ncol;
        float* r1 = out + (size_t)(mrow + mt * 16 + 8) * NDIM + ncol;
        #pragma unroll
        for (int nt = 0; nt < 8; nt++) {
            float2 v0 = make_float2(acc[mt][nt][0] + bv[nt].x, acc[mt][nt][1] + bv[nt].y);
            float2 v1 = make_float2(acc[mt][nt][2] + bv[nt].x, acc[mt][nt][3] + bv[nt].y);
            *reinterpret_cast<float2*>(r0 + nt * 8) = v0;
            *reinterpret_cast<float2*>(r1 + nt * 8) = v1;
        }
    }
}

// ---------------- launch ----------------------------------------------------
extern "C" void kernel_launch(void* const* d_in, const int* in_sizes, int n_in,
                              void* d_out, int out_size) {
    const float* x    = (const float*)d_in[0];
    const int*   qw   = (const int*)d_in[1];
    const float* ws   = (const float*)d_in[2];
    const float* pd   = (const float*)d_in[3];
    const float* pu   = (const float*)d_in[4];
    const float* wt   = (const float*)d_in[5];
    const float* bias = (const float*)d_in[6];
    float* out = (float*)d_out;

    // x -> tf32 (RNA) into g_x
    {
        float* gx;
        cudaGetSymbolAddress((void**)&gx, g_x);
        int n4 = (MDIM * KDIM) / 4;
        round_x_kernel<<<n4 / 256, 256>>>((const float4*)x, (float4*)gx);
    }
    // W_eff = dequant + lora, tf32-rounded
    prep_weight_kernel<<<dim3(KDIM / 512, NDIM / 16), 256>>>(qw, ws, pd, pu, wt);

    // main GEMM
    cudaFuncSetAttribute(gemm_tf32_kernel, cudaFuncAttributeMaxDynamicSharedMemorySize, SMEM_TOTAL);
    gemm_tf32_kernel<<<dim3(NDIM / BN, MDIM / BM), 128, SMEM_TOTAL>>>(bias, out);
}

// round 3
// speedup vs baseline: 2.9417x; 2.9417x over previous
#include <cuda_runtime.h>
#include <cuda_fp16.h>
#include <cstdint>

// Problem dims (fixed by the dataset)
#define MDIM 8192
#define KDIM 4096
#define NDIM 4096

// ---------------- device scratch (sanctioned: __device__ globals) ----------
__device__ __half g_weffh[(size_t)NDIM * KDIM];  // 32 MB: dequant + lora folded, fp16
__device__ __half g_xh[(size_t)MDIM * KDIM];     // 64 MB: x rounded to fp16 (RN)

// ---------------- helpers ---------------------------------------------------
__device__ __forceinline__ uint32_t smem_u32(const void* p) {
    uint32_t a;
    asm("{ .reg .u64 t; cvta.to.shared.u64 t, %1; cvt.u32.u64 %0, t; }" : "=r"(a) : "l"(p));
    return a;
}
__device__ __forceinline__ void cp16(uint32_t dst, const void* src) {
    asm volatile("cp.async.cg.shared.global [%0], [%1], 16;" :: "r"(dst), "l"(src));
}
__device__ __forceinline__ void cp_commit() {
    asm volatile("cp.async.commit_group;" ::: "memory");
}
template <int N>
__device__ __forceinline__ void cp_wait() {
    asm volatile("cp.async.wait_group %0;" :: "n"(N) : "memory");
}
__device__ __forceinline__ void ldsm4(uint32_t r[4], uint32_t addr) {
    asm volatile("ldmatrix.sync.aligned.m8n8.x4.shared.b16 {%0,%1,%2,%3}, [%4];"
                 : "=r"(r[0]), "=r"(r[1]), "=r"(r[2]), "=r"(r[3]) : "r"(addr));
}
__device__ __forceinline__ void mma16(float c[4], const uint32_t a[4],
                                      uint32_t b0, uint32_t b1) {
    asm volatile("mma.sync.aligned.m16n8k16.row.col.f32.f16.f16.f32 "
                 "{%0,%1,%2,%3}, {%4,%5,%6,%7}, {%8,%9}, {%0,%1,%2,%3};"
                 : "+f"(c[0]), "+f"(c[1]), "+f"(c[2]), "+f"(c[3])
                 : "r"(a[0]), "r"(a[1]), "r"(a[2]), "r"(a[3]), "r"(b0), "r"(b1));
}

// ---------------- kernel 1: round x to fp16 (RN) ----------------------------
__global__ void __launch_bounds__(256) round_x_kernel(const float4* __restrict__ x,
                                                      __half2* __restrict__ gx) {
    int i = blockIdx.x * 256 + threadIdx.x;
    float4 v = x[i];
    gx[2 * i + 0] = __floats2half2_rn(v.x, v.y);
    gx[2 * i + 1] = __floats2half2_rn(v.z, v.w);
}

// ---------------- kernel 2: W_eff = dequant(q,scale) + wtscale * up@down ---
__global__ void __launch_bounds__(256) prep_weight_kernel(
    const int* __restrict__ qweight, const float* __restrict__ wscales,
    const float* __restrict__ proj_down, const float* __restrict__ proj_up,
    const float* __restrict__ wtscale)
{
    __shared__ float up_s[16 * 32];
    const int n0 = blockIdx.y * 16;
    const int tid = threadIdx.x;
    #pragma unroll
    for (int j = tid; j < 512; j += 256) {
        int n = j >> 5, r = j & 31;
        up_s[j] = proj_up[(size_t)(n0 + n) * 32 + r];
    }
    __syncthreads();
    const float wt = wtscale[0];
    const int k2 = blockIdx.x * 256 + tid;   // pair index; k = 2*k2, 2*k2+1

    float ae[16], ao[16];
    #pragma unroll
    for (int n = 0; n < 16; n++) { ae[n] = 0.f; ao[n] = 0.f; }
    #pragma unroll 4
    for (int r = 0; r < 32; r++) {
        float2 d2 = *reinterpret_cast<const float2*>(proj_down + (size_t)r * KDIM + 2 * k2);
        #pragma unroll
        for (int n = 0; n < 16; n++) {
            float u = up_s[n * 32 + r];
            ae[n] = fmaf(u, d2.x, ae[n]);
            ao[n] = fmaf(u, d2.y, ao[n]);
        }
    }
    const int g = k2 >> 5;  // (2*k2)/64
    #pragma unroll
    for (int n = 0; n < 16; n++) {
        int q = qweight[(size_t)(n0 + n) * (KDIM / 2) + k2];
        float s = wscales[(size_t)g * NDIM + (n0 + n)];
        float we = fmaf((float)((q & 15) - 8), s, wt * ae[n]);
        float wo = fmaf((float)(((q >> 4) & 15) - 8), s, wt * ao[n]);
        *reinterpret_cast<__half2*>(g_weffh + (size_t)(n0 + n) * KDIM + 2 * k2) =
            __floats2half2_rn(we, wo);
    }
}

// ---------------- kernel 3: fp16 mma.sync GEMM ------------------------------
// out[m0:m0+128, n0:n0+128] = g_xh @ g_weffh^T + bias   (fp32 accumulate)
#define BM 128
#define BN 128
#define BK 64
#define STAGES 3
#define KTILES (KDIM / BK)            // 64
#define A_BYTES (BM * BK * 2)         // 16384
#define STAGE_BYTES (2 * A_BYTES)     // 32768 (A then B)
#define SMEM_TOTAL (STAGES * STAGE_BYTES)

__global__ void __launch_bounds__(128, 2) gemm_fp16_kernel(
    const float* __restrict__ bias, float* __restrict__ out)
{
    extern __shared__ char smem_raw[];
    const uint32_t sbase = smem_u32(smem_raw);

    const int tid  = threadIdx.x;
    const int lane = tid & 31;
    const int warp = tid >> 5;
    const int wm = warp & 1;          // 2 warps in m -> warp tile 64 rows
    const int wn = warp >> 1;         // 2 warps in n -> warp tile 64 cols
    const int m0 = blockIdx.y * BM;
    const int n0 = blockIdx.x * BN;

    // ---- cp.async source/dest (thread t owns A row t and B row t) ----
    const char* srcA = (const char*)(g_xh    + (size_t)(m0 + tid) * KDIM);
    const char* srcB = (const char*)(g_weffh + (size_t)(n0 + tid) * KDIM);
    const uint32_t dstRow = sbase + (uint32_t)tid * 128;  // within-stage row base (128B rows)
    const int rsw = tid & 7;                               // store swizzle

    // ---- ldmatrix per-lane addressing ----
    const int lr = lane & 7;
    const int g1 = (lane >> 3) & 1;
    const int g2 = lane >> 4;
    // A x4: (a0: m0-7 k0-7 | a1: m8-15 k0-7 | a2: m0-7 k8-15 | a3: m8-15 k8-15)
    const uint32_t aOff = (uint32_t)(wm * 64 + lr + (g1 << 3)) * 128;
    // B x4: (b0,b1 of n-tile p | b0,b1 of n-tile p+1): row += 8 on g2, chunk += 1 on g1
    const uint32_t bOff = (uint32_t)(wn * 64 + lr + (g2 << 3)) * 128;

    float acc[4][8][4];
    #pragma unroll
    for (int i = 0; i < 4; i++)
        #pragma unroll
        for (int j = 0; j < 8; j++)
            #pragma unroll
            for (int c = 0; c < 4; c++) acc[i][j][c] = 0.f;

    // ---- stage loader: 8 chunks x 16B per row = 64 halves (BK) ----
    auto load_stage = [&](int st, int kt) {
        uint32_t sa = dstRow + (uint32_t)st * STAGE_BYTES;
        const char* ga = srcA + (size_t)kt * (BK * 2);
        const char* gb = srcB + (size_t)kt * (BK * 2);
        #pragma unroll
        for (int c = 0; c < 8; c++) {
            uint32_t off = (uint32_t)((c ^ rsw) << 4);
            cp16(sa + off,           ga + c * 16);
            cp16(sa + A_BYTES + off, gb + c * 16);
        }
    };

    // ---- prologue: prefetch 2 stages ----
    load_stage(0, 0); cp_commit();
    load_stage(1, 1); cp_commit();

    int st = 0;
    for (int kt = 0; kt < KTILES; kt++) {
        cp_wait<1>();
        __syncthreads();

        if (kt + 2 < KTILES) {
            int st2 = st + 2; if (st2 >= STAGES) st2 -= STAGES;
            load_stage(st2, kt + 2);
        }
        cp_commit();

        const uint32_t aSt = sbase + (uint32_t)st * STAGE_BYTES + aOff;
        const uint32_t bSt = sbase + (uint32_t)st * STAGE_BYTES + A_BYTES + bOff;

        #pragma unroll
        for (int s = 0; s < 4; s++) {           // 4 k-steps of k16 (2 chunks each)
            uint32_t a[4][4], b[4][4];
            const uint32_t xA = (uint32_t)(((2 * s + g2) ^ lr) << 4);
            const uint32_t xB = (uint32_t)(((2 * s + g1) ^ lr) << 4);
            #pragma unroll
            for (int mt = 0; mt < 4; mt++) ldsm4(a[mt], aSt + mt * 2048 + xA);
            #pragma unroll
            for (int p = 0; p < 4; p++)    ldsm4(b[p], bSt + p * 2048 + xB);
            #pragma unroll
            for (int mt = 0; mt < 4; mt++) {
                #pragma unroll
                for (int p = 0; p < 4; p++) {
                    mma16(acc[mt][2 * p],     a[mt], b[p][0], b[p][1]);
                    mma16(acc[mt][2 * p + 1], a[mt], b[p][2], b[p][3]);
                }
            }
        }
        if (++st == STAGES) st = 0;
    }

    // ---- epilogue: add bias, store float2 ----
    const int mrow = m0 + wm * 64 + (lane >> 2);
    const int ncol = n0 + wn * 64 + 2 * (lane & 3);
    float2 bv[8];
    #pragma unroll
    for (int nt = 0; nt < 8; nt++)
        bv[nt] = *reinterpret_cast<const float2*>(bias + ncol + nt * 8);

    #pragma unroll
    for (int mt = 0; mt < 4; mt++) {
        float* r0 = out + (size_t)(mrow + mt * 16) * NDIM + ncol;
        float* r1 = out + (size_t)(mrow + mt * 16 + 8) * NDIM + ncol;
        #pragma unroll
        for (int nt = 0; nt < 8; nt++) {
            float2 v0 = make_float2(acc[mt][nt][0] + bv[nt].x, acc[mt][nt][1] + bv[nt].y);
            float2 v1 = make_float2(acc[mt][nt][2] + bv[nt].x, acc[mt][nt][3] + bv[nt].y);
            *reinterpret_cast<float2*>(r0 + nt * 8) = v0;
            *reinterpret_cast<float2*>(r1 + nt * 8) = v1;
        }
    }
}

// ---------------- launch ----------------------------------------------------
extern "C" void kernel_launch(void* const* d_in, const int* in_sizes, int n_in,
                              void* d_out, int out_size) {
    const float* x    = (const float*)d_in[0];
    const int*   qw   = (const int*)d_in[1];
    const float* ws   = (const float*)d_in[2];
    const float* pd   = (const float*)d_in[3];
    const float* pu   = (const float*)d_in[4];
    const float* wt   = (const float*)d_in[5];
    const float* bias = (const float*)d_in[6];
    float* out = (float*)d_out;

    // x -> fp16 (RN) into g_xh
    {
        __half2* gx;
        cudaGetSymbolAddress((void**)&gx, g_xh);
        int n4 = (MDIM * KDIM) / 4;
        round_x_kernel<<<n4 / 256, 256>>>((const float4*)x, gx);
    }
    // W_eff = dequant + lora, fp16-rounded
    prep_weight_kernel<<<dim3(KDIM / 512, NDIM / 16), 256>>>(qw, ws, pd, pu, wt);

    // main GEMM
    cudaFuncSetAttribute(gemm_fp16_kernel, cudaFuncAttributeMaxDynamicSharedMemorySize, SMEM_TOTAL);
    gemm_fp16_kernel<<<dim3(NDIM / BN, MDIM / BM), 128, SMEM_TOTAL>>>(bias, out);
}

// round 4
// speedup vs baseline: 3.1705x; 1.0778x over previous
#include <cuda_runtime.h>
#include <cuda_fp16.h>
#include <cstdint>

// Problem dims (fixed by the dataset)
#define MDIM 8192
#define KDIM 4096
#define NDIM 4096

// ---------------- device scratch (sanctioned: __device__ globals) ----------
__device__ __half g_weffh[(size_t)NDIM * KDIM];  // 32 MB: dequant + lora folded, fp16
__device__ __half g_xh[(size_t)MDIM * KDIM];     // 64 MB: x rounded to fp16 (RN)

// ---------------- helpers ---------------------------------------------------
__device__ __forceinline__ uint32_t smem_u32(const void* p) {
    uint32_t a;
    asm("{ .reg .u64 t; cvta.to.shared.u64 t, %1; cvt.u32.u64 %0, t; }" : "=r"(a) : "l"(p));
    return a;
}
__device__ __forceinline__ void cp16(uint32_t dst, const void* src) {
    asm volatile("cp.async.cg.shared.global [%0], [%1], 16;" :: "r"(dst), "l"(src));
}
__device__ __forceinline__ void cp_commit() {
    asm volatile("cp.async.commit_group;" ::: "memory");
}
template <int N>
__device__ __forceinline__ void cp_wait() {
    asm volatile("cp.async.wait_group %0;" :: "n"(N) : "memory");
}
__device__ __forceinline__ void ldsm4(uint32_t r[4], uint32_t addr) {
    asm volatile("ldmatrix.sync.aligned.m8n8.x4.shared.b16 {%0,%1,%2,%3}, [%4];"
                 : "=r"(r[0]), "=r"(r[1]), "=r"(r[2]), "=r"(r[3]) : "r"(addr));
}
__device__ __forceinline__ void mma16(float c[4], const uint32_t a[4],
                                      uint32_t b0, uint32_t b1) {
    asm volatile("mma.sync.aligned.m16n8k16.row.col.f32.f16.f16.f32 "
                 "{%0,%1,%2,%3}, {%4,%5,%6,%7}, {%8,%9}, {%0,%1,%2,%3};"
                 : "+f"(c[0]), "+f"(c[1]), "+f"(c[2]), "+f"(c[3])
                 : "r"(a[0]), "r"(a[1]), "r"(a[2]), "r"(a[3]), "r"(b0), "r"(b1));
}

// ---------------- kernel 1: round x to fp16 (RN) ----------------------------
__global__ void __launch_bounds__(256) round_x_kernel(const float4* __restrict__ x,
                                                      __half2* __restrict__ gx) {
    int i = blockIdx.x * 256 + threadIdx.x;
    float4 v = x[i];
    gx[2 * i + 0] = __floats2half2_rn(v.x, v.y);
    gx[2 * i + 1] = __floats2half2_rn(v.z, v.w);
}

// ---------------- kernel 2: W_eff = dequant(q,scale) + wtscale * up@down ---
__global__ void __launch_bounds__(256) prep_weight_kernel(
    const int* __restrict__ qweight, const float* __restrict__ wscales,
    const float* __restrict__ proj_down, const float* __restrict__ proj_up,
    const float* __restrict__ wtscale)
{
    __shared__ float up_s[16 * 32];
    const int n0 = blockIdx.y * 16;
    const int tid = threadIdx.x;
    #pragma unroll
    for (int j = tid; j < 512; j += 256) {
        int n = j >> 5, r = j & 31;
        up_s[j] = proj_up[(size_t)(n0 + n) * 32 + r];
    }
    __syncthreads();
    const float wt = wtscale[0];
    const int k2 = blockIdx.x * 256 + tid;   // pair index; k = 2*k2, 2*k2+1

    float ae[16], ao[16];
    #pragma unroll
    for (int n = 0; n < 16; n++) { ae[n] = 0.f; ao[n] = 0.f; }
    #pragma unroll 4
    for (int r = 0; r < 32; r++) {
        float2 d2 = *reinterpret_cast<const float2*>(proj_down + (size_t)r * KDIM + 2 * k2);
        #pragma unroll
        for (int n = 0; n < 16; n++) {
            float u = up_s[n * 32 + r];
            ae[n] = fmaf(u, d2.x, ae[n]);
            ao[n] = fmaf(u, d2.y, ao[n]);
        }
    }
    const int g = k2 >> 5;  // (2*k2)/64
    #pragma unroll
    for (int n = 0; n < 16; n++) {
        int q = qweight[(size_t)(n0 + n) * (KDIM / 2) + k2];
        float s = wscales[(size_t)g * NDIM + (n0 + n)];
        float we = fmaf((float)((q & 15) - 8), s, wt * ae[n]);
        float wo = fmaf((float)(((q >> 4) & 15) - 8), s, wt * ao[n]);
        *reinterpret_cast<__half2*>(g_weffh + (size_t)(n0 + n) * KDIM + 2 * k2) =
            __floats2half2_rn(we, wo);
    }
}

// ---------------- kernel 3: fp16 mma.sync GEMM ------------------------------
// out[m0:m0+128, n0:n0+128] = g_xh @ g_weffh^T + bias   (fp32 accumulate)
// Register-fragment double buffering to keep the HMMA pipe fed across
// k-step boundaries and the cp.async/syncthreads tile boundary.
#define BM 128
#define BN 128
#define BK 64
#define STAGES 3
#define KTILES (KDIM / BK)            // 64
#define A_BYTES (BM * BK * 2)         // 16384
#define STAGE_BYTES (2 * A_BYTES)     // 32768 (A then B)
#define SMEM_TOTAL (STAGES * STAGE_BYTES)

__global__ void __launch_bounds__(128, 2) gemm_fp16_kernel(
    const float* __restrict__ bias, float* __restrict__ out)
{
    extern __shared__ char smem_raw[];
    const uint32_t sbase = smem_u32(smem_raw);

    const int tid  = threadIdx.x;
    const int lane = tid & 31;
    const int warp = tid >> 5;
    const int wm = warp & 1;          // 2 warps in m -> warp tile 64 rows
    const int wn = warp >> 1;         // 2 warps in n -> warp tile 64 cols
    const int m0 = blockIdx.y * BM;
    const int n0 = blockIdx.x * BN;

    // ---- cp.async source/dest (thread t owns A row t and B row t) ----
    const char* srcA = (const char*)(g_xh    + (size_t)(m0 + tid) * KDIM);
    const char* srcB = (const char*)(g_weffh + (size_t)(n0 + tid) * KDIM);
    const uint32_t dstRow = sbase + (uint32_t)tid * 128;  // within-stage row base (128B rows)
    const int rsw = tid & 7;                               // store swizzle

    // ---- ldmatrix per-lane addressing ----
    const int lr = lane & 7;
    const int g1 = (lane >> 3) & 1;
    const int g2 = lane >> 4;
    const uint32_t aOff = (uint32_t)(wm * 64 + lr + (g1 << 3)) * 128;
    const uint32_t bOff = (uint32_t)(wn * 64 + lr + (g2 << 3)) * 128;

    float acc[4][8][4];
    #pragma unroll
    for (int i = 0; i < 4; i++)
        #pragma unroll
        for (int j = 0; j < 8; j++)
            #pragma unroll
            for (int c = 0; c < 4; c++) acc[i][j][c] = 0.f;

    // ---- stage loader: 8 chunks x 16B per row = 64 halves (BK) ----
    auto load_stage = [&](int st, int kt) {
        uint32_t sa = dstRow + (uint32_t)st * STAGE_BYTES;
        const char* ga = srcA + (size_t)kt * (BK * 2);
        const char* gb = srcB + (size_t)kt * (BK * 2);
        #pragma unroll
        for (int c = 0; c < 8; c++) {
            uint32_t off = (uint32_t)((c ^ rsw) << 4);
            cp16(sa + off,           ga + c * 16);
            cp16(sa + A_BYTES + off, gb + c * 16);
        }
    };

    // fragment double buffers
    uint32_t fa[2][4][4], fb[2][4][4];

    // load all fragments of k-step s from stage st into buffer buf
    auto ldsm_step = [&](int buf, int st, int s) {
        const uint32_t aSt = sbase + (uint32_t)st * STAGE_BYTES + aOff;
        const uint32_t bSt = sbase + (uint32_t)st * STAGE_BYTES + A_BYTES + bOff;
        const uint32_t xA = (uint32_t)(((2 * s + g2) ^ lr) << 4);
        const uint32_t xB = (uint32_t)(((2 * s + g1) ^ lr) << 4);
        #pragma unroll
        for (int mt = 0; mt < 4; mt++) {
            ldsm4(fa[buf][mt], aSt + mt * 2048 + xA);
            ldsm4(fb[buf][mt], bSt + mt * 2048 + xB);
        }
    };

    auto mma_step = [&](int buf) {
        #pragma unroll
        for (int mt = 0; mt < 4; mt++) {
            #pragma unroll
            for (int p = 0; p < 4; p++) {
                mma16(acc[mt][2 * p],     fa[buf][mt], fb[buf][p][0], fb[buf][p][1]);
                mma16(acc[mt][2 * p + 1], fa[buf][mt], fb[buf][p][2], fb[buf][p][3]);
            }
        }
    };

    // ---- prologue: prefetch 2 stages, then preload step-0 fragments ----
    load_stage(0, 0); cp_commit();
    load_stage(1, 1); cp_commit();
    cp_wait<1>();
    __syncthreads();
    ldsm_step(0, 0, 0);

    int st = 0;
    for (int kt = 0; kt < KTILES; kt++) {
        // prefetch kt+2 into the stage consumed at kt-1
        if (kt + 2 < KTILES) {
            int st2 = st + 2; if (st2 >= STAGES) st2 -= STAGES;
            load_stage(st2, kt + 2);
        }
        cp_commit();

        int stn = st + 1; if (stn >= STAGES) stn = 0;

        #pragma unroll
        for (int s = 0; s < 4; s++) {
            const int cur = s & 1;
            if (s < 3) {
                ldsm_step(cur ^ 1, st, s + 1);   // prefetch next step's fragments
                mma_step(cur);
            } else {
                mma_step(cur);                    // issue last MMAs before the sync
                if (kt + 1 < KTILES) {
                    cp_wait<1>();
                    __syncthreads();
                    ldsm_step(cur ^ 1, stn, 0);   // preload next tile's step 0
                }
            }
        }
        st = stn;
    }

    // ---- epilogue: add bias, store float2 ----
    const int mrow = m0 + wm * 64 + (lane >> 2);
    const int ncol = n0 + wn * 64 + 2 * (lane & 3);
    float2 bv[8];
    #pragma unroll
    for (int nt = 0; nt < 8; nt++)
        bv[nt] = *reinterpret_cast<const float2*>(bias + ncol + nt * 8);

    #pragma unroll
    for (int mt = 0; mt < 4; mt++) {
        float* r0 = out + (size_t)(mrow + mt * 16) * NDIM + ncol;
        float* r1 = out + (size_t)(mrow + mt * 16 + 8) * NDIM + ncol;
        #pragma unroll
        for (int nt = 0; nt < 8; nt++) {
            float2 v0 = make_float2(acc[mt][nt][0] + bv[nt].x, acc[mt][nt][1] + bv[nt].y);
            float2 v1 = make_float2(acc[mt][nt][2] + bv[nt].x, acc[mt][nt][3] + bv[nt].y);
            *reinterpret_cast<float2*>(r0 + nt * 8) = v0;
            *reinterpret_cast<float2*>(r1 + nt * 8) = v1;
        }
    }
}

// ---------------- launch ----------------------------------------------------
extern "C" void kernel_launch(void* const* d_in, const int* in_sizes, int n_in,
                              void* d_out, int out_size) {
    const float* x    = (const float*)d_in[0];
    const int*   qw   = (const int*)d_in[1];
    const float* ws   = (const float*)d_in[2];
    const float* pd   = (const float*)d_in[3];
    const float* pu   = (const float*)d_in[4];
    const float* wt   = (const float*)d_in[5];
    const float* bias = (const float*)d_in[6];
    float* out = (float*)d_out;

    // x -> fp16 (RN) into g_xh
    {
        __half2* gx;
        cudaGetSymbolAddress((void**)&gx, g_xh);
        int n4 = (MDIM * KDIM) / 4;
        round_x_kernel<<<n4 / 256, 256>>>((const float4*)x, gx);
    }
    // W_eff = dequant + lora, fp16-rounded
    prep_weight_kernel<<<dim3(KDIM / 512, NDIM / 16), 256>>>(qw, ws, pd, pu, wt);

    // main GEMM
    cudaFuncSetAttribute(gemm_fp16_kernel, cudaFuncAttributeMaxDynamicSharedMemorySize, SMEM_TOTAL);
    gemm_fp16_kernel<<<dim3(NDIM / BN, MDIM / BM), 128, SMEM_TOTAL>>>(bias, out);
}